// round 17
// baseline (speedup 1.0000x reference)
#include <cuda_runtime.h>
#include <cuda_fp16.h>
#include <cstdint>

#define NN 50000
#define DD 64
#define NE 800000

// ---- scratch (__device__ globals; allocation-free rule) ----
__device__ unsigned short g_csrc[NE];    // CSR: src per edge (src < 65536)
__device__ unsigned int   g_rankdst[NE]; // packed (rank<<16)|dst per edge
__device__ int   g_deg[NN];      // invariant: zero at entry of every call
__device__ int   g_off[NN];      // per-block-exclusive offsets
__device__ int   g_bsum[256];    // global-exclusive block offsets
__device__ int   g_done;         // invariant: zero at entry of every call
__device__ __align__(16) __half g_t[NN * DD];   // t1 = x @ W1nbr (fp16)
__device__ __align__(16) __half g_t2[NN * DD];  // t2 = relu(h1) @ W2nbr (fp16)
__device__ __align__(16) float  g_h[NN * DD];   // gemm1 root output (fp32)

// ---------------------------------------------------------------------------
// Per-block int64-vs-int32 detection (odd 32-bit words all zero => int64).
// ---------------------------------------------------------------------------
__device__ __forceinline__ int detect_idx64(const unsigned* words) {
    __shared__ int nz;
    if (threadIdx.x == 0) nz = 0;
    __syncthreads();
    if (threadIdx.x < 256 && words[2 * threadIdx.x + 1] != 0u) nz = 1;
    __syncthreads();
    return nz ? 0 : 1;
}

// ---------------------------------------------------------------------------
// hist + rank: the ONLY atomic pass. Stores packed (rank<<16)|dst.
// ---------------------------------------------------------------------------
__global__ void __launch_bounds__(256) hist_rank_kernel(const void* __restrict__ idx, int E) {
    int idx64 = detect_idx64((const unsigned*)idx);
    int i = blockIdx.x * blockDim.x + threadIdx.x;
    if (i >= E) return;
    int d;
    if (idx64) d = (int)((const long long*)idx)[(size_t)E + i];
    else       d = ((const int*)idx)[(size_t)E + i];
    int rank = atomicAdd(&g_deg[d], 1);
    g_rankdst[i] = ((unsigned)rank << 16) | (unsigned)d;
}

// ---------------------------------------------------------------------------
// Multi-block scan (coalesced): per-block exclusive into g_off, block sums
// scanned by last-arriving block into g_bsum. Zeroes g_deg, resets g_done.
// ---------------------------------------------------------------------------
__global__ void scan1_kernel(int nblocks, int n) {
    __shared__ int sh[256];
    int tid = threadIdx.x;
    int i = blockIdx.x * 256 + tid;
    int v = 0;
    if (i < n) {
        v = g_deg[i];
        g_deg[i] = 0;            // restore invariant for next call
    }
    sh[tid] = v;
    __syncthreads();
#pragma unroll
    for (int off = 1; off < 256; off <<= 1) {
        int x = (tid >= off) ? sh[tid - off] : 0;
        __syncthreads();
        sh[tid] += x;
        __syncthreads();
    }
    if (i < n) g_off[i] = sh[tid] - v;           // exclusive within block
    if (tid == 255) g_bsum[blockIdx.x] = sh[255];

    __shared__ int is_last;
    __threadfence();
    if (tid == 0) is_last = (atomicAdd(&g_done, 1) == nblocks - 1) ? 1 : 0;
    __syncthreads();
    if (is_last) {
        int bv = (tid < nblocks) ? g_bsum[tid] : 0;
        sh[tid] = bv;
        __syncthreads();
#pragma unroll
        for (int off = 1; off < 256; off <<= 1) {
            int x = (tid >= off) ? sh[tid - off] : 0;
            __syncthreads();
            sh[tid] += x;
            __syncthreads();
        }
        if (tid < nblocks) g_bsum[tid] = sh[tid] - bv;   // global-exclusive
        if (tid == 0) g_done = 0;                        // restore invariant
    }
}

// ---------------------------------------------------------------------------
// place: no atomics. pos = off_local[dst] + bsum[dst>>8] + rank.
// ---------------------------------------------------------------------------
__global__ void __launch_bounds__(256) place_kernel(const void* __restrict__ idx, int E) {
    int idx64 = detect_idx64((const unsigned*)idx);
    int e = blockIdx.x * blockDim.x + threadIdx.x;
    if (e >= E) return;
    int s;
    if (idx64) s = (int)((const long long*)idx)[e];
    else       s = ((const int*)idx)[e];
    unsigned rd = g_rankdst[e];
    int d = (int)(rd & 0xFFFFu);
    int rank = (int)(rd >> 16);
    int pos = __ldg(&g_off[d]) + __ldg(&g_bsum[d >> 8]) + rank;
    g_csrc[pos] = (unsigned short)s;
}

// ---------------------------------------------------------------------------
// Shared MMA machinery.
// ---------------------------------------------------------------------------
__device__ __forceinline__ uint32_t smem_u32(const void* p) {
    return (uint32_t)__cvta_generic_to_shared(p);
}
__device__ __forceinline__ void ldm_x4(uint32_t* r, uint32_t addr) {
    asm volatile("ldmatrix.sync.aligned.m8n8.x4.shared.b16 {%0,%1,%2,%3}, [%4];"
                 : "=r"(r[0]), "=r"(r[1]), "=r"(r[2]), "=r"(r[3]) : "r"(addr));
}
__device__ __forceinline__ void ldm_x4_t(uint32_t* r, uint32_t addr) {
    asm volatile("ldmatrix.sync.aligned.m8n8.x4.trans.shared.b16 {%0,%1,%2,%3}, [%4];"
                 : "=r"(r[0]), "=r"(r[1]), "=r"(r[2]), "=r"(r[3]) : "r"(addr));
}
__device__ __forceinline__ void mma16816(float* c, const uint32_t* a,
                                         uint32_t b0, uint32_t b1) {
    asm volatile(
        "mma.sync.aligned.m16n8k16.row.col.f32.f16.f16.f32 "
        "{%0,%1,%2,%3}, {%4,%5,%6,%7}, {%8,%9}, {%0,%1,%2,%3};"
        : "+f"(c[0]), "+f"(c[1]), "+f"(c[2]), "+f"(c[3])
        : "r"(a[0]), "r"(a[1]), "r"(a[2]), "r"(a[3]), "r"(b0), "r"(b1));
}

#define CPAD 68   // fp32 C stage row stride (floats)
#define HPAD 72   // fp16 C stage row stride (halves)

// stage W = [Wroot | Wnbr] into sW (64 rows x 16 chunks, swizzled)
__device__ __forceinline__ void stage_w(__half* sW, const float* Wroot,
                                        const float* Wnbr, int tid) {
#pragma unroll
    for (int i = 0; i < 4; i++) {
        int idx = tid + 256 * i;
        int k = idx >> 4;
        int c16 = idx & 15;
        const float* src = (c16 < 8) ? (Wroot + k * 64 + c16 * 8)
                                     : (Wnbr + k * 64 + (c16 - 8) * 8);
        float4 v0 = ((const float4*)src)[0];
        float4 v1 = ((const float4*)src)[1];
        __half2 hp[4];
        hp[0] = __floats2half2_rn(v0.x, v0.y);
        hp[1] = __floats2half2_rn(v0.z, v0.w);
        hp[2] = __floats2half2_rn(v1.x, v1.y);
        hp[3] = __floats2half2_rn(v1.z, v1.w);
        *(uint4*)&sW[k * 128 + ((c16 ^ (k & 7)) << 3)] = *(uint4*)hp;
    }
}

// mma core + coalesced two-phase epilogue (operates on sX/sW, writes Omain/Ot)
__device__ __forceinline__ void mma_and_epilogue(
    __half* sX, __half* sW, float* sC, __half* sC2, const float* sBias,
    float* Omain, __half* Ot, int row0, int n, int tid)
{
    const int lane = tid & 31;
    const int wid = tid >> 5;
    const int warp_m = wid & 3;
    const int warp_n = wid >> 2;
    const int m_base = warp_m * 32;
    const int n_base = warp_n * 64;

    float c[2][8][4];
#pragma unroll
    for (int tm = 0; tm < 2; tm++)
#pragma unroll
        for (int nt = 0; nt < 8; nt++)
#pragma unroll
            for (int q = 0; q < 4; q++) c[tm][nt][q] = 0.f;

    const uint32_t sX_base = smem_u32(sX);
    const uint32_t sW_base = smem_u32(sW);

#pragma unroll
    for (int ks = 0; ks < 4; ks++) {
        uint32_t a[2][4];
#pragma unroll
        for (int tm = 0; tm < 2; tm++) {
            int rl = m_base + tm * 16 + (lane & 15);
            int kchunk = ks * 2 + (lane >> 4);
            uint32_t off = rl * 64 + ((kchunk ^ (rl & 7)) << 3);
            ldm_x4(a[tm], sX_base + off * 2);
        }
        uint32_t b[4][4];
#pragma unroll
        for (int np = 0; np < 4; np++) {
            int rk = ks * 16 + (lane & 15);
            int nchunk = (n_base >> 3) + np * 2 + (lane >> 4);
            uint32_t off = rk * 128 + ((nchunk ^ (rk & 7)) << 3);
            ldm_x4_t(b[np], sW_base + off * 2);
        }
#pragma unroll
        for (int tm = 0; tm < 2; tm++)
#pragma unroll
            for (int np = 0; np < 4; np++) {
                mma16816(c[tm][2 * np],     a[tm], b[np][0], b[np][1]);
                mma16816(c[tm][2 * np + 1], a[tm], b[np][2], b[np][3]);
            }
    }

    const int groupID = lane >> 2;
    const int tq = lane & 3;

    // epilogue A: Omain (fp32 + bias) via smem, coalesced
    __syncthreads();
    if (warp_n == 0) {
#pragma unroll
        for (int tm = 0; tm < 2; tm++) {
#pragma unroll
            for (int nt = 0; nt < 8; nt++) {
                int col = nt * 8 + tq * 2;
                float2 bv = *(float2*)&sBias[col];
                int r0 = m_base + tm * 16 + groupID;
                *(float2*)&sC[r0 * CPAD + col] =
                    make_float2(c[tm][nt][0] + bv.x, c[tm][nt][1] + bv.y);
                *(float2*)&sC[(r0 + 8) * CPAD + col] =
                    make_float2(c[tm][nt][2] + bv.x, c[tm][nt][3] + bv.y);
            }
        }
    }
    __syncthreads();
#pragma unroll
    for (int i = 0; i < 8; i++) {
        int idx = tid + 256 * i;
        int r = idx >> 4;
        int c16 = idx & 15;
        int grow = row0 + r;
        if (grow < n)
            *(uint4*)(Omain + (size_t)grow * 64 + c16 * 4) =
                *(uint4*)&sC[r * CPAD + c16 * 4];
    }

    // epilogue B: Ot (fp16) via smem, coalesced
    __syncthreads();
    if (warp_n == 1) {
#pragma unroll
        for (int tm = 0; tm < 2; tm++) {
#pragma unroll
            for (int nt = 0; nt < 8; nt++) {
                int col = nt * 8 + tq * 2;
                int r0 = m_base + tm * 16 + groupID;
                *(__half2*)&sC2[r0 * HPAD + col] =
                    __floats2half2_rn(c[tm][nt][0], c[tm][nt][1]);
                *(__half2*)&sC2[(r0 + 8) * HPAD + col] =
                    __floats2half2_rn(c[tm][nt][2], c[tm][nt][3]);
            }
        }
    }
    __syncthreads();
#pragma unroll
    for (int i = 0; i < 4; i++) {
        int idx = tid + 256 * i;
        int r = idx >> 3;
        int c8 = idx & 7;
        int grow = row0 + r;
        if (grow < n)
            *(uint4*)(Ot + (size_t)grow * 64 + c8 * 8) =
                *(uint4*)&sC2[r * HPAD + c8 * 8];
    }
}

// ---------------------------------------------------------------------------
// Layer-1 GEMM (R14-proven): stage X from global fp32, mma, coalesced epi.
// ---------------------------------------------------------------------------
__global__ void __launch_bounds__(256) gemm1_kernel(
    const float* __restrict__ X,
    const float* __restrict__ Wroot,
    const float* __restrict__ Wnbr,
    const float* __restrict__ bias,
    float* __restrict__ Omain,
    __half* __restrict__ Ot,
    int n)
{
    __shared__ __align__(16) char smem_buf[128 * CPAD * 4];
    __shared__ float sBias[64];
    __half* sX = (__half*)smem_buf;
    __half* sW = (__half*)(smem_buf + 16384);
    float*  sC  = (float*)smem_buf;
    __half* sC2 = (__half*)smem_buf;

    const int tid = threadIdx.x;
    const int row0 = blockIdx.x * 128;

#pragma unroll
    for (int i = 0; i < 4; i++) {
        int idx = tid + 256 * i;
        int r = idx >> 3;
        int c8 = idx & 7;
        int grow = row0 + r;
        float4 v0 = make_float4(0.f, 0.f, 0.f, 0.f), v1 = v0;
        if (grow < n) {
            const float4* xr = (const float4*)X + (size_t)grow * 16;
            v0 = xr[c8 * 2]; v1 = xr[c8 * 2 + 1];
        }
        __half2 hp[4];
        hp[0] = __floats2half2_rn(v0.x, v0.y);
        hp[1] = __floats2half2_rn(v0.z, v0.w);
        hp[2] = __floats2half2_rn(v1.x, v1.y);
        hp[3] = __floats2half2_rn(v1.z, v1.w);
        *(uint4*)&sX[r * 64 + ((c8 ^ (r & 7)) << 3)] = *(uint4*)hp;
    }
    stage_w(sW, Wroot, Wnbr, tid);
    if (tid < 64) sBias[tid] = bias[tid];
    __syncthreads();

    mma_and_epilogue(sX, sW, sC, sC2, sBias, Omain, Ot, row0, n, tid);
}

// ---------------------------------------------------------------------------
// FUSED agg1 + layer-2 GEMM: gather sum(t1[src]) in registers, add gemm1's
// root output h, relu, convert fp16 -> staged sX; then mma + epilogue.
// NOTE: Ot here MUST be a distinct buffer from t (WAR hazard across CTAs).
// ---------------------------------------------------------------------------
__global__ void __launch_bounds__(256) fused_agg_gemm2_kernel(
    const float* __restrict__ h,
    const __half* __restrict__ t,
    const float* __restrict__ Wroot,
    const float* __restrict__ Wnbr,
    const float* __restrict__ bias,
    float* __restrict__ Omain,
    __half* __restrict__ Ot,
    int n, int E)
{
    __shared__ __align__(16) char smem_buf[128 * CPAD * 4];
    __shared__ float sBias[64];
    __half* sX = (__half*)smem_buf;
    __half* sW = (__half*)(smem_buf + 16384);
    float*  sC  = (float*)smem_buf;
    __half* sC2 = (__half*)smem_buf;

    const int tid = threadIdx.x;
    const int row0 = blockIdx.x * 128;

    stage_w(sW, Wroot, Wnbr, tid);
    if (tid < 64) sBias[tid] = bias[tid];

    // ---- gather + build sX ----
    const int part = tid & 7;
    const int grp = tid >> 3;          // 0..31
    const uint4* tH = (const uint4*)t;

#pragma unroll
    for (int rr = 0; rr < 4; rr++) {
        int rloc = grp + rr * 32;      // 0..127
        int node = row0 + rloc;
        __half2 hp[4];
        if (node < n) {
            // root part from h (includes b1)
            float acc[8];
            const float4* hr = (const float4*)(h + (size_t)node * 64 + part * 8);
            float4 h0 = hr[0], h1 = hr[1];
            acc[0] = h0.x; acc[1] = h0.y; acc[2] = h0.z; acc[3] = h0.w;
            acc[4] = h1.x; acc[5] = h1.y; acc[6] = h1.z; acc[7] = h1.w;

            int start = __ldg(&g_off[node]) + __ldg(&g_bsum[node >> 8]);
            int end = (node == n - 1)
                        ? E
                        : __ldg(&g_off[node + 1]) + __ldg(&g_bsum[(node + 1) >> 8]);

            int j = start;
            for (; j + 4 <= end; j += 4) {
                int s0 = (int)__ldg(&g_csrc[j]);
                int s1 = (int)__ldg(&g_csrc[j + 1]);
                int s2 = (int)__ldg(&g_csrc[j + 2]);
                int s3 = (int)__ldg(&g_csrc[j + 3]);
                uint4 v0 = tH[(size_t)s0 * 8 + part];
                uint4 v1 = tH[(size_t)s1 * 8 + part];
                uint4 v2 = tH[(size_t)s2 * 8 + part];
                uint4 v3 = tH[(size_t)s3 * 8 + part];
                const uint4 vv[4] = {v0, v1, v2, v3};
#pragma unroll
                for (int q = 0; q < 4; q++) {
                    const __half2* hq = (const __half2*)&vv[q];
#pragma unroll
                    for (int cc = 0; cc < 4; cc++) {
                        float2 f = __half22float2(hq[cc]);
                        acc[2 * cc]     += f.x;
                        acc[2 * cc + 1] += f.y;
                    }
                }
            }
            for (; j < end; j++) {
                int s = (int)__ldg(&g_csrc[j]);
                uint4 v = tH[(size_t)s * 8 + part];
                const __half2* hq = (const __half2*)&v;
#pragma unroll
                for (int cc = 0; cc < 4; cc++) {
                    float2 f = __half22float2(hq[cc]);
                    acc[2 * cc]     += f.x;
                    acc[2 * cc + 1] += f.y;
                }
            }
            // relu + cvt fp16
#pragma unroll
            for (int q = 0; q < 8; q++) acc[q] = fmaxf(acc[q], 0.f);
            hp[0] = __floats2half2_rn(acc[0], acc[1]);
            hp[1] = __floats2half2_rn(acc[2], acc[3]);
            hp[2] = __floats2half2_rn(acc[4], acc[5]);
            hp[3] = __floats2half2_rn(acc[6], acc[7]);
        } else {
            hp[0] = hp[1] = hp[2] = hp[3] = __floats2half2_rn(0.f, 0.f);
        }
        *(uint4*)&sX[rloc * 64 + ((part ^ (rloc & 7)) << 3)] = *(uint4*)hp;
    }
    __syncthreads();

    mma_and_epilogue(sX, sW, sC, sC2, sBias, Omain, Ot, row0, n, tid);
}

// ---------------------------------------------------------------------------
// Final CSR gather-aggregate (fp16 t2): out[i] += sum t2[csrc[...]]
// ---------------------------------------------------------------------------
__global__ void __launch_bounds__(256) agg_kernel(
    const __half* __restrict__ t, float* __restrict__ out, int n, int E)
{
    int gid = blockIdx.x * blockDim.x + threadIdx.x;
    int node = gid >> 3;
    if (node >= n) return;
    int part = threadIdx.x & 7;

    int start = __ldg(&g_off[node]) + __ldg(&g_bsum[node >> 8]);
    int end = (node == n - 1)
                ? E
                : __ldg(&g_off[node + 1]) + __ldg(&g_bsum[(node + 1) >> 8]);

    const uint4* tH = (const uint4*)t;
    float acc[8] = {0.f, 0.f, 0.f, 0.f, 0.f, 0.f, 0.f, 0.f};

    int j = start;
    for (; j + 4 <= end; j += 4) {
        int s0 = (int)__ldg(&g_csrc[j]);
        int s1 = (int)__ldg(&g_csrc[j + 1]);
        int s2 = (int)__ldg(&g_csrc[j + 2]);
        int s3 = (int)__ldg(&g_csrc[j + 3]);
        uint4 r0 = tH[(size_t)s0 * 8 + part];
        uint4 r1 = tH[(size_t)s1 * 8 + part];
        uint4 r2 = tH[(size_t)s2 * 8 + part];
        uint4 r3 = tH[(size_t)s3 * 8 + part];
        const uint4 rr[4] = {r0, r1, r2, r3};
#pragma unroll
        for (int q = 0; q < 4; q++) {
            const __half2* hp = (const __half2*)&rr[q];
#pragma unroll
            for (int cidx = 0; cidx < 4; cidx++) {
                float2 f = __half22float2(hp[cidx]);
                acc[2 * cidx]     += f.x;
                acc[2 * cidx + 1] += f.y;
            }
        }
    }
    for (; j < end; j++) {
        int s = (int)__ldg(&g_csrc[j]);
        uint4 r = tH[(size_t)s * 8 + part];
        const __half2* hp = (const __half2*)&r;
#pragma unroll
        for (int cidx = 0; cidx < 4; cidx++) {
            float2 f = __half22float2(hp[cidx]);
            acc[2 * cidx]     += f.x;
            acc[2 * cidx + 1] += f.y;
        }
    }

    float4* o4 = (float4*)(out + (size_t)node * 64 + part * 8);
    float4 c0 = o4[0], c1 = o4[1];
    c0.x += acc[0]; c0.y += acc[1]; c0.z += acc[2]; c0.w += acc[3];
    c1.x += acc[4]; c1.y += acc[5]; c1.z += acc[6]; c1.w += acc[7];
    o4[0] = c0; o4[1] = c1;
}

// ---------------------------------------------------------------------------
extern "C" void kernel_launch(void* const* d_in, const int* in_sizes, int n_in,
                              void* d_out, int out_size)
{
    const float* x      = (const float*)d_in[0];
    const void*  eidx   = d_in[1];
    const float* W1root = (const float*)d_in[2];
    const float* W1nbr  = (const float*)d_in[3];
    const float* b1     = (const float*)d_in[4];
    const float* W2root = (const float*)d_in[5];
    const float* W2nbr  = (const float*)d_in[6];
    const float* b2     = (const float*)d_in[7];
    float* out = (float*)d_out;

    const int n = in_sizes[0] / DD;     // 50000
    const int E = in_sizes[1] / 2;      // 800000

    float* hptr;
    __half *tptr, *t2ptr;
    cudaGetSymbolAddress((void**)&hptr, g_h);
    cudaGetSymbolAddress((void**)&tptr, g_t);
    cudaGetSymbolAddress((void**)&t2ptr, g_t2);

    const int edge_blocks = (E + 255) / 256;
    const int scan_blocks = (n + 255) / 256;          // 196
    const int gemm_blocks = (n + 127) / 128;
    const int agg_blocks  = (n * 8 + 255) / 256;

    static cudaStream_t s_side = nullptr;
    static cudaEvent_t  ev_fork = nullptr, ev_join = nullptr;
    if (s_side == nullptr) {
        cudaStreamCreateWithFlags(&s_side, cudaStreamNonBlocking);
        cudaEventCreateWithFlags(&ev_fork, cudaEventDisableTiming);
        cudaEventCreateWithFlags(&ev_join, cudaEventDisableTiming);
    }

    // ---- fork: CSR build on side stream, concurrent with gemm1 ----
    cudaEventRecord(ev_fork, cudaStreamPerThread);
    cudaStreamWaitEvent(s_side, ev_fork, 0);

    hist_rank_kernel<<<edge_blocks, 256, 0, s_side>>>(eidx, E);
    scan1_kernel    <<<scan_blocks, 256, 0, s_side>>>(scan_blocks, n);
    place_kernel    <<<edge_blocks, 256, 0, s_side>>>(eidx, E);
    cudaEventRecord(ev_join, s_side);

    // ---- main stream: layer-1 GEMM in parallel with CSR build ----
    gemm1_kernel<<<gemm_blocks, 256>>>(x, W1root, W1nbr, b1, hptr, tptr, n);

    // join: fused kernel needs CSR, h, t1. Writes out (root part) + t2.
    cudaStreamWaitEvent(cudaStreamPerThread, ev_join, 0);
    fused_agg_gemm2_kernel<<<gemm_blocks, 256>>>(hptr, tptr, W2root, W2nbr, b2,
                                                 out, t2ptr, n, E);

    // ---- final aggregation: out += gather(t2) ----
    agg_kernel<<<agg_blocks, 256>>>(t2ptr, out, n, E);
}